// round 5
// baseline (speedup 1.0000x reference)
#include <cuda_runtime.h>
#include <math.h>
#include <stdint.h>

#define Bn   8
#define HWn  1024
#define NEGn 256

// ---------------- device scratch ----------------------------------------------
__device__ __align__(16) unsigned g_z1b[Bn * HWn * 32];   // bf16x2 pixel-major, 128B rows
__device__ __align__(16) unsigned g_z2b[Bn * HWn * 32];
__device__ float g_rz1n[Bn * HWn];
__device__ float g_rz2n[Bn * HWn];
__device__ float g_z1sq[Bn * HWn];
__device__ __align__(16) float4 g_imgt[HWn];
__device__ __align__(16) signed char g_gs[(size_t)Bn * HWn * HWn]; // 8MB cos table (int8 x127)
__device__ float g_pn [Bn * 16 * NEGn];
__device__ float g_s0p[Bn * 16];
__device__ unsigned g_ticket;

__device__ __forceinline__ uint32_t smem_to_u32(const void* p) {
    uint32_t a;
    asm("{ .reg .u64 t; cvta.to.shared.u64 t, %1; cvt.u32.u64 %0, t; }" : "=r"(a) : "l"(p));
    return a;
}
#define SMEM_SWIZZLE_128B(o) ((o) ^ (((o) >> 3) & 0x70))

__device__ __forceinline__ unsigned bf16rn(float f) {
    unsigned u = __float_as_uint(f);
    return (u + 0x7FFFu + ((u >> 16) & 1u)) >> 16;
}

__device__ __forceinline__ void ldsm_x4(uint32_t& r0, uint32_t& r1, uint32_t& r2,
                                        uint32_t& r3, uint32_t addr) {
    asm volatile("ldmatrix.sync.aligned.m8n8.x4.shared.b16 {%0,%1,%2,%3}, [%4];"
                 : "=r"(r0), "=r"(r1), "=r"(r2), "=r"(r3) : "r"(addr));
}
__device__ __forceinline__ void ldsm_x2(uint32_t& r0, uint32_t& r1, uint32_t addr) {
    asm volatile("ldmatrix.sync.aligned.m8n8.x2.shared.b16 {%0,%1}, [%2];"
                 : "=r"(r0), "=r"(r1) : "r"(addr));
}
__device__ __forceinline__ void mma16816(float* c, const uint32_t* a, const uint32_t* b) {
    asm volatile("mma.sync.aligned.m16n8k16.row.col.f32.bf16.bf16.f32 "
                 "{%0,%1,%2,%3}, {%4,%5,%6,%7}, {%8,%9}, {%0,%1,%2,%3};"
                 : "+f"(c[0]), "+f"(c[1]), "+f"(c[2]), "+f"(c[3])
                 : "r"(a[0]), "r"(a[1]), "r"(a[2]), "r"(a[3]), "r"(b[0]), "r"(b[1]));
}

__device__ __forceinline__ signed char quant127(float x) {
    float v = fminf(fmaxf(x, -127.0f), 127.0f);
    return (signed char)__float2int_rn(v);
}

// ---------------- prep: transpose to bf16 pixel-major + norms + img ------------
// grid (32 qtiles, 8 b, 2 views), 256 threads. Norms computed from the
// QUANTIZED values so |cos| <= 1 holds for the GEMM outputs.
__global__ void prep_kernel(const float* __restrict__ z1,
                            const float* __restrict__ z2,
                            const float* __restrict__ img) {
    __shared__ float ts[64][33];
    __shared__ float psum[8][32];
    const int s  = blockIdx.z;
    const int b  = blockIdx.y;
    const int q0 = blockIdx.x * 32;
    const int t  = threadIdx.x;
    const int lane = t & 31, wr = t >> 5;

    if (s == 0 && b == 0) {
        if (blockIdx.x == 0 && t == 0) g_ticket = 0;   // reset last-block ticket
        if (t < 32) {
            int q = q0 + t;
            g_imgt[q] = make_float4(img[q], img[HWn + q], img[2 * HWn + q], 0.f);
        }
    }

    const float* zp = s ? z2 : z1;
    float acc = 0.f;
    #pragma unroll
    for (int k = 0; k < 8; k++) {
        int c = k * 8 + wr;
        float v = zp[((b * 64 + c) << 10) + q0 + lane];
        float vq = __uint_as_float(bf16rn(v) << 16);   // quantized value
        ts[c][lane] = vq;
        acc += vq * vq;
    }
    psum[wr][lane] = acc;
    __syncthreads();

    if (t < 32) {
        float sum = 0.f;
        #pragma unroll
        for (int i = 0; i < 8; i++) sum += psum[i][t];
        int gi = (b << 10) + q0 + t;
        if (s == 0) { g_z1sq[gi] = sum; g_rz1n[gi] = rsqrtf(sum); }
        else        { g_rz2n[gi] = rsqrtf(sum); }
    }

    unsigned* outp = s ? g_z2b : g_z1b;
    #pragma unroll
    for (int k = 0; k < 4; k++) {
        int idx = k * 256 + t;
        int j = idx >> 5, cp = idx & 31;
        unsigned lo = bf16rn(ts[2 * cp][j]);
        unsigned hi = bf16rn(ts[2 * cp + 1][j]);
        outp[(((b << 10) + q0 + j) << 5) + cp] = lo | (hi << 16);
    }
}

// ---------------- GEMM: G[b][p][q] = round(127*cos(z1_p, z2_q)) int8 -----------
// grid (8 qtile, 8 ptile, 8 b), 256 threads (8 warps, 2x4 warp grid)
#define SM_AS    0
#define SM_BS    16384
#define SM_STG   32768
#define STG_PITCH 144                        // 128B data + 16B pad, keeps 16B align
#define SM_RZ1   (SM_STG + 128 * STG_PITCH)  // 51200
#define SM_RZ2   (SM_RZ1 + 512)
#define SM_GEMM_TOTAL (SM_RZ2 + 512)         // 52224

__global__ void __launch_bounds__(256) gemm_kernel() {
    extern __shared__ char smem[];
    const uint32_t sb = smem_to_u32(smem);
    const int t = threadIdx.x, w = t >> 5, lane = t & 31;
    const int qtile = blockIdx.x, ptile = blockIdx.y, b = blockIdx.z;
    const int wm = w >> 2, wn = w & 3;          // warp tile: 64 p x 32 q

    // load A tile (128 p-rows x 128B) and B tile (128 q-rows x 128B), SW128 swizzle
    {
        const uint4* srcA = (const uint4*)g_z1b + (((size_t)(b << 10) + (ptile << 7)) << 3);
        const uint4* srcB = (const uint4*)g_z2b + (((size_t)(b << 10) + (qtile << 7)) << 3);
        #pragma unroll
        for (int it = 0; it < 4; it++) {
            int u = it * 256 + t;
            uint32_t off = SMEM_SWIZZLE_128B((uint32_t)(u * 16));
            *(uint4*)(smem + SM_AS + off) = srcA[u];
            *(uint4*)(smem + SM_BS + off) = srcB[u];
        }
    }
    if (t < 128) {
        ((float*)(smem + SM_RZ1))[t] = g_rz1n[(b << 10) + (ptile << 7) + t];
        ((float*)(smem + SM_RZ2))[t] = g_rz2n[(b << 10) + (qtile << 7) + t];
    }
    __syncthreads();

    float c[4][4][4];
    #pragma unroll
    for (int mi = 0; mi < 4; mi++)
        #pragma unroll
        for (int ni = 0; ni < 4; ni++)
            #pragma unroll
            for (int r = 0; r < 4; r++) c[mi][ni][r] = 0.f;

    #pragma unroll
    for (int ks = 0; ks < 4; ks++) {
        uint32_t a[4][4], bb[4][2];
        #pragma unroll
        for (int mi = 0; mi < 4; mi++) {
            int row  = (wm << 6) + (mi << 4) + (lane & 15);
            int half = lane >> 4;
            uint32_t off = SMEM_SWIZZLE_128B((uint32_t)(row * 128 + ks * 32 + half * 16));
            ldsm_x4(a[mi][0], a[mi][1], a[mi][2], a[mi][3], sb + SM_AS + off);
        }
        #pragma unroll
        for (int ni = 0; ni < 4; ni++) {
            int row  = (wn << 5) + (ni << 3) + (lane & 7);
            int half = (lane >> 3) & 1;
            uint32_t off = SMEM_SWIZZLE_128B((uint32_t)(row * 128 + ks * 32 + half * 16));
            ldsm_x2(bb[ni][0], bb[ni][1], sb + SM_BS + off);
        }
        #pragma unroll
        for (int mi = 0; mi < 4; mi++)
            #pragma unroll
            for (int ni = 0; ni < 4; ni++)
                mma16816(c[mi][ni], a[mi], bb[ni]);
    }

    // epilogue: scale by 127*rz1*rz2, quantize to int8, write to padded stage
    {
        char* stg = smem + SM_STG;
        const float* rz1s = (const float*)(smem + SM_RZ1);
        const float* rz2s = (const float*)(smem + SM_RZ2);
        #pragma unroll
        for (int mi = 0; mi < 4; mi++) {
            int r0 = (wm << 6) + (mi << 4) + (lane >> 2);
            int r1 = r0 + 8;
            float z1a = rz1s[r0] * 127.0f, z1b = rz1s[r1] * 127.0f;
            #pragma unroll
            for (int ni = 0; ni < 4; ni++) {
                int cq = (wn << 5) + (ni << 3) + ((lane & 3) << 1);
                float rq0 = rz2s[cq], rq1 = rz2s[cq + 1];
                int ia0 = (int)(unsigned char)quant127(c[mi][ni][0] * z1a * rq0);
                int ia1 = (int)(unsigned char)quant127(c[mi][ni][1] * z1a * rq1);
                int ib0 = (int)(unsigned char)quant127(c[mi][ni][2] * z1b * rq0);
                int ib1 = (int)(unsigned char)quant127(c[mi][ni][3] * z1b * rq1);
                *(unsigned short*)(stg + r0 * STG_PITCH + cq) =
                    (unsigned short)(ia0 | (ia1 << 8));
                *(unsigned short*)(stg + r1 * STG_PITCH + cq) =
                    (unsigned short)(ib0 | (ib1 << 8));
            }
        }
    }
    __syncthreads();

    // coalesced store: 128 rows x 128B int8
    {
        const char* stg = smem + SM_STG;
        #pragma unroll
        for (int it = 0; it < 4; it++) {
            int row  = it * 32 + (t >> 3);
            int colb = (t & 7) << 4;
            uint4 v = *(const uint4*)(stg + row * STG_PITCH + colb);
            size_t off = ((size_t)(b << 10) + (ptile << 7) + row) << 10;
            *(uint4*)(g_gs + off + (qtile << 7) + colb) = v;
        }
    }
}

// ---------------- gather + merged final reduction -------------------------------
__global__ void __launch_bounds__(1024, 1)
gather_kernel(const int* __restrict__ neg_idx, float* __restrict__ out, int out_size) {
    __shared__ float4 imgt_sm[HWn];     // 16 KB
    __shared__ float  dot_sm[32][NEGn]; // 32 KB
    __shared__ float  s0w[32];
    __shared__ float  r1s[32], r2s[32];
    __shared__ float  lb[8], s0b[8], s2b[8];
    __shared__ unsigned is_last;

    const int b    = blockIdx.x;
    const int by   = blockIdx.y;
    const int t    = threadIdx.x;
    const int w    = t >> 5;
    const int lane = t & 31;

    imgt_sm[t] = g_imgt[t];
    __syncthreads();

    const float INV_EUC   = 1.0f / sqrtf((float)(31 * 31 + 31 * 31));
    const float INV_SQRT3 = 0.57735026919f;

    float acc[8];
    #pragma unroll
    for (int r = 0; r < 8; r++) acc[r] = 0.f;
    float sim0acc = 0.f;

    const signed char* gcb = g_gs + ((size_t)b << 20);

    #pragma unroll 1
    for (int it = 0; it < 2; it++) {
        const int p = (by << 6) + (w << 1) + it;
        const float z1sqp = g_z1sq[(b << 10) + p];
        const float hp = (float)(p >> 5), wp = (float)(p & 31);
        const float4 ctr = imgt_sm[p];

        const int* negH = neg_idx + ((size_t)(b * 2) << 18) + (p << 8);
        const int* negW = negH + (1 << 18);

        int qn[8];
        float eucsq = 0.f, rgbsq = 0.f;
        #pragma unroll
        for (int r = 0; r < 8; r++) {
            int n  = (r << 5) + lane;
            int nh = negH[n];
            int nw = negW[n];
            int q  = (nh << 5) + nw;
            qn[r] = q;
            float dh = hp - (float)nh, dw = wp - (float)nw;
            eucsq += dh * dh; eucsq += dw * dw;
            float4 c4 = imgt_sm[q];
            float dr = ctr.x - c4.x, dg = ctr.y - c4.y, db = ctr.z - c4.z;
            rgbsq += dr * dr; rgbsq += dg * dg; rgbsq += db * db;
        }
        #pragma unroll
        for (int s = 16; s > 0; s >>= 1) {
            eucsq += __shfl_xor_sync(0xffffffffu, eucsq, s);
            rgbsq += __shfl_xor_sync(0xffffffffu, rgbsq, s);
        }
        const float weight = 0.8f * sqrtf(eucsq) * INV_EUC
                           + 0.2f * sqrtf(rgbsq) * INV_SQRT3;
        const float wscale = weight * (1.0f / 127.0f);

        const signed char* grow = gcb + ((size_t)p << 10);
        #pragma unroll
        for (int r = 0; r < 8; r++) {
            float g = (float)grow[qn[r]];
            acc[r] += fminf(fabsf(g * wscale), 1.0f);
        }
        if (lane == 0) {
            float c0 = z1sqp / fmaxf(z1sqp, 1e-8f);
            sim0acc += fminf(fabsf(c0), 1.0f);
        }
    }

    #pragma unroll
    for (int r = 0; r < 8; r++) dot_sm[w][(r << 5) + lane] = acc[r];
    if (lane == 0) s0w[w] = sim0acc;
    __syncthreads();

    if (t < NEGn) {
        float s = 0.f;
        #pragma unroll
        for (int k = 0; k < 32; k++) s += dot_sm[k][t];
        g_pn[(((b << 4) + by) << 8) + t] = s;
    }
    if (t == 0) {
        float s = 0.f;
        #pragma unroll
        for (int k = 0; k < 32; k++) s += s0w[k];
        g_s0p[(b << 4) + by] = s;
    }

    // ---- last-block final reduction (threadFenceReduction pattern) ----
    __threadfence();
    __syncthreads();
    if (t == 0) is_last = (atomicAdd(&g_ticket, 1u) == (unsigned)(Bn * 16 - 1));
    __syncthreads();
    if (!is_last) return;
    __threadfence();

    {
        const int fb = t >> 7;     // 128 threads per sample
        const int j  = t & 127;

        float v1 = 0.f, v2 = 0.f;
        #pragma unroll
        for (int h = 0; h < 2; h++) {
            int n = j + (h << 7);
            float s = 0.f;
            #pragma unroll
            for (int k = 0; k < 16; k++)
                s += __ldcg(&g_pn[(((fb << 4) + k) << 8) + n]);
            float sn = s * (0.5f / 1024.0f);
            v2 += sn;
            v1 += fmaxf(log1pf(-sn), -100.0f);
        }
        #pragma unroll
        for (int s = 16; s > 0; s >>= 1) {
            v1 += __shfl_xor_sync(0xffffffffu, v1, s);
            v2 += __shfl_xor_sync(0xffffffffu, v2, s);
        }
        if ((t & 31) == 0) { r1s[t >> 5] = v1; r2s[t >> 5] = v2; }
        __syncthreads();

        if (t < 8) {
            float s1 = r1s[4 * t] + r1s[4 * t + 1] + r1s[4 * t + 2] + r1s[4 * t + 3];
            float s2 = r2s[4 * t] + r2s[4 * t + 1] + r2s[4 * t + 2] + r2s[4 * t + 3];
            float s0s = 0.f;
            #pragma unroll
            for (int k = 0; k < 16; k++) s0s += __ldcg(&g_s0p[(t << 4) + k]);
            float s0   = s0s * (1.0f / 1024.0f);
            float logp = fmaxf(logf(s0), -100.0f);
            lb[t]  = -(logp + s1) * (1.0f / 257.0f);
            s0b[t] = s0;
            s2b[t] = s2;
        }
        __syncthreads();

        if (t == 0) {
            float loss = 0.f, o1 = 0.f, o2 = 0.f;
            #pragma unroll
            for (int i = 0; i < 8; i++) { loss += lb[i]; o1 += s0b[i]; o2 += s2b[i]; }
            if (out_size > 0) out[0] = loss * 0.125f;
            if (out_size > 1) out[1] = o1 * 0.125f;
            if (out_size > 2) out[2] = o2 * (2.0f / (256.0f * 8.0f));
        }
    }
}

// ---------------- launch --------------------------------------------------------
extern "C" void kernel_launch(void* const* d_in, const int* in_sizes, int n_in,
                              void* d_out, int out_size) {
    const float* v1   = (const float*)d_in[0];
    const float* v2   = (const float*)d_in[1];
    const float* img  = (const float*)d_in[2];
    const int*   nidx = (const int*)  d_in[3];

    cudaFuncSetAttribute(gemm_kernel, cudaFuncAttributeMaxDynamicSharedMemorySize,
                         SM_GEMM_TOTAL);

    prep_kernel<<<dim3(32, 8, 2), 256>>>(v1, v2, img);
    gemm_kernel<<<dim3(8, 8, 8), 256, SM_GEMM_TOTAL>>>();
    gather_kernel<<<dim3(Bn, 16), 1024>>>(nidx, (float*)d_out, out_size);
}